// round 1
// baseline (speedup 1.0000x reference)
#include <cuda_runtime.h>
#include <cuda_bf16.h>

#define BB 64
#define NENT 512
#define DENT 256
#define WDIM 64

// ---------------- scratch (device globals; no allocations) ----------------
__device__ float g_h0[BB*50*WDIM*WDIM];   // concat [B,50,64,64]
__device__ float g_h1[BB*32*WDIM*WDIM];   // after project
__device__ float g_h2[BB*64*32*32];       // after ds1
__device__ float g_h3[BB*128*16*16];      // after ds2
__device__ float g_h [BB*128*8*8];        // running h (after ds3 / res blocks)
__device__ float g_o1[BB*128*8*8];        // res conv1 out
__device__ float g_o2[BB*128*8*8];        // res conv2 out
__device__ float g_scale[128];
__device__ float g_shift[128];

// ---------------- concat init: zero scatter channels, copy x ----------------
__global__ void k_init_concat(const float* __restrict__ x) {
    int idx = blockIdx.x * blockDim.x + threadIdx.x;
    const int per_b = 50 * 4096;
    int b = idx / per_b;
    int r = idx - b * per_b;
    int c = r >> 12;
    int p = r & 4095;
    g_h0[idx] = (c < 32) ? 0.f : x[(b * 18 + (c - 32)) * 4096 + p];
}

// ---------------- scatter: warp per entity ----------------
__global__ void k_scatter(const float* __restrict__ emb, const int* __restrict__ xy,
                          const float* __restrict__ w1) {
    __shared__ float s_wT[256 * 33];
    int tid = threadIdx.x;
    for (int i = tid; i < 32 * 256; i += blockDim.x) {
        int c = i >> 8;
        int d = i & 255;
        s_wT[d * 33 + c] = w1[i];
    }
    __syncthreads();
    int warp = blockIdx.x * (blockDim.x >> 5) + (tid >> 5);
    int lane = tid & 31;
    if (warp >= BB * NENT) return;
    int b = warp / NENT;
    int n = warp - b * NENT;
    const int* bits = xy + (size_t)(b * NENT + n) * 16;
    if (bits[0] == -1000000000) return;   // invalid entity contributes nothing
    int bit = (lane < 16) ? bits[lane] : 0;
    int contrib;
    if (lane < 8)       contrib = bit << (7 - lane);          // x bits
    else if (lane < 16) contrib = bit << (31 - lane);          // y bits at <<16
    else                contrib = 0;
    int pack = __reduce_add_sync(0xffffffffu, contrib);
    int xv = (pack & 0xffff) >> 2;
    int yv = (pack >> 16) >> 2;
    const float4* e4 = reinterpret_cast<const float4*>(emb + (size_t)(b * NENT + n) * 256);
    float acc = 0.f;
#pragma unroll 8
    for (int i = 0; i < 64; i++) {
        float4 v = e4[i];   // warp-uniform 16B load
        acc += v.x * s_wT[(4 * i + 0) * 33 + lane];
        acc += v.y * s_wT[(4 * i + 1) * 33 + lane];
        acc += v.z * s_wT[(4 * i + 2) * 33 + lane];
        acc += v.w * s_wT[(4 * i + 3) * 33 + lane];
    }
    acc = fmaxf(acc, 0.f);
    if (acc != 0.f)
        atomicAdd(&g_h0[(b * 50 + lane) * 4096 + yv * 64 + xv], acc);
}

// ---------------- project 1x1 conv 50->32 + relu ----------------
__global__ void k_proj(const float* __restrict__ pw, const float* __restrict__ pb) {
    __shared__ float s_pw[32 * 50];
    __shared__ float s_pb[32];
    int tid = threadIdx.x;
    for (int i = tid; i < 1600; i += blockDim.x) s_pw[i] = pw[i];
    if (tid < 32) s_pb[tid] = pb[tid];
    __syncthreads();
    int idx = blockIdx.x * blockDim.x + tid;   // (b, cg, p): p fastest
    int p  = idx & 4095;
    int cg = (idx >> 12) & 3;
    int b  = idx >> 14;
    float acc[8];
#pragma unroll
    for (int j = 0; j < 8; j++) acc[j] = 0.f;
    const float* src = g_h0 + (size_t)b * 50 * 4096 + p;
    for (int ci = 0; ci < 50; ci++) {
        float v = src[ci * 4096];
#pragma unroll
        for (int j = 0; j < 8; j++)
            acc[j] = fmaf(v, s_pw[(cg * 8 + j) * 50 + ci], acc[j]);
    }
    float* dst = g_h1 + ((size_t)b * 32 + cg * 8) * 4096 + p;
#pragma unroll
    for (int j = 0; j < 8; j++)
        dst[j * 4096] = fmaxf(acc[j] + s_pb[cg * 8 + j], 0.f);
}

// ---------------- down conv: k=4, s=2, p=1, +bias, +relu ----------------
template<int CIN, int HIN, int COUT, int TCO, int TOW, int TOH, int CC>
__global__ __launch_bounds__((COUT/TCO)*((HIN/2)/TOW))
void k_downconv(const float* __restrict__ in, const float* __restrict__ wt,
                const float* __restrict__ bias, float* __restrict__ out,
                float* __restrict__ out2) {
    constexpr int HO    = HIN / 2;
    constexpr int NCOG  = COUT / TCO;
    constexpr int NOWG  = HO / TOW;
    constexpr int NROWS = 2 * TOH + 2;
    constexpr int NTHR  = NCOG * NOWG;
    __shared__ float s_in[NROWS * CC * HIN];
    __shared__ float s_w[CC * 16 * (COUT + 1)];
    const int b   = blockIdx.y;
    const int oh0 = blockIdx.x * TOH;
    const int tid = threadIdx.x;
    const int cog = tid % NCOG;
    const int owg = tid / NCOG;
    const int co0 = cog * TCO;
    const int ow0 = owg * TOW;
    const int ihbase = 2 * oh0 - 1;
    float acc[TCO][TOH][TOW];
#pragma unroll
    for (int t = 0; t < TCO; t++)
#pragma unroll
        for (int o = 0; o < TOH; o++)
#pragma unroll
            for (int w = 0; w < TOW; w++) acc[t][o][w] = 0.f;

#pragma unroll 1
    for (int ci0 = 0; ci0 < CIN; ci0 += CC) {
        __syncthreads();
        for (int i = tid; i < NROWS * CC * HIN; i += NTHR) {
            int r   = i / (CC * HIN);
            int rem = i - r * CC * HIN;
            int cc  = rem / HIN;
            int xx  = rem - cc * HIN;
            int ih  = ihbase + r;
            s_in[i] = (ih >= 0 && ih < HIN)
                    ? in[(((size_t)b * CIN + ci0 + cc) * HIN + ih) * HIN + xx] : 0.f;
        }
        for (int i = tid; i < CC * 16 * COUT; i += NTHR) {
            int co  = i / (CC * 16);
            int k16 = i - co * CC * 16;
            s_w[k16 * (COUT + 1) + co] = wt[((size_t)co * CIN + ci0) * 16 + k16];
        }
        __syncthreads();
#pragma unroll 1
        for (int cc = 0; cc < CC; cc++) {
#pragma unroll
            for (int kh = 0; kh < 4; kh++) {
                float wr[TCO][4];
#pragma unroll
                for (int t = 0; t < TCO; t++)
#pragma unroll
                    for (int kw = 0; kw < 4; kw++)
                        wr[t][kw] = s_w[(cc * 16 + kh * 4 + kw) * (COUT + 1) + co0 + t];
#pragma unroll
                for (int ot = 0; ot < TOH; ot++) {
                    const float* srow = &s_in[((2 * ot + kh) * CC + cc) * HIN];
                    float xr[2 * TOW + 2];
#pragma unroll
                    for (int j = 0; j < 2 * TOW + 2; j++) {
                        int iw = 2 * ow0 - 1 + j;
                        xr[j] = (iw >= 0 && iw < HIN) ? srow[iw] : 0.f;
                    }
#pragma unroll
                    for (int t = 0; t < TCO; t++)
#pragma unroll
                        for (int w = 0; w < TOW; w++)
#pragma unroll
                            for (int kw = 0; kw < 4; kw++)
                                acc[t][ot][w] = fmaf(xr[2 * w + kw], wr[t][kw], acc[t][ot][w]);
                }
            }
        }
    }
#pragma unroll
    for (int t = 0; t < TCO; t++) {
        float bv = bias[co0 + t];
#pragma unroll
        for (int ot = 0; ot < TOH; ot++)
#pragma unroll
            for (int w = 0; w < TOW; w++) {
                float v = fmaxf(acc[t][ot][w] + bv, 0.f);
                size_t o = (((size_t)b * COUT + co0 + t) * HO + oh0 + ot) * HO + ow0 + w;
                out[o] = v;
                if (out2) out2[o] = v;
            }
    }
}

// ---------------- res conv 3x3 p1 on 8x8, 128->128, raw (BN after) ----------------
__global__ __launch_bounds__(128)
void k_resconv(const float* __restrict__ in, const float* __restrict__ wt,
               float* __restrict__ out) {
    constexpr int COC = 32;
    constexpr int CC  = 16;
    __shared__ float s_img[CC * 100];           // [cc][10 rows][10 cols], zero-padded
    __shared__ float s_w[CC * 9 * (COC + 1)];
    const int b    = blockIdx.y;
    const int co0  = blockIdx.x * COC;
    const int tid  = threadIdx.x;
    const int co_l = tid & 31;
    const int ohp  = tid >> 5;
    const int oh0  = ohp * 2;
    float acc[2][8];
#pragma unroll
    for (int o = 0; o < 2; o++)
#pragma unroll
        for (int w = 0; w < 8; w++) acc[o][w] = 0.f;

#pragma unroll 1
    for (int ci0 = 0; ci0 < 128; ci0 += CC) {
        __syncthreads();
        for (int i = tid; i < CC * 100; i += 128) {
            int cc  = i / 100;
            int rem = i - cc * 100;
            int r   = rem / 10;
            int cl  = rem - r * 10;
            int ih = r - 1, iw = cl - 1;
            s_img[i] = (ih >= 0 && ih < 8 && iw >= 0 && iw < 8)
                     ? in[(((size_t)b * 128 + ci0 + cc) * 8 + ih) * 8 + iw] : 0.f;
        }
        for (int i = tid; i < CC * 9 * COC; i += 128) {
            int co = i / (CC * 9);
            int k9 = i - co * CC * 9;
            s_w[k9 * (COC + 1) + co] = wt[((size_t)(co0 + co) * 128 + ci0) * 9 + k9];
        }
        __syncthreads();
#pragma unroll 1
        for (int cc = 0; cc < CC; cc++) {
            float wr[9];
#pragma unroll
            for (int k = 0; k < 9; k++) wr[k] = s_w[(cc * 9 + k) * (COC + 1) + co_l];
            float xr[4][10];
#pragma unroll
            for (int r = 0; r < 4; r++)
#pragma unroll
                for (int cl = 0; cl < 10; cl++)
                    xr[r][cl] = s_img[cc * 100 + (oh0 + r) * 10 + cl];
#pragma unroll
            for (int ot = 0; ot < 2; ot++)
#pragma unroll
                for (int kh = 0; kh < 3; kh++)
#pragma unroll
                    for (int ow = 0; ow < 8; ow++)
#pragma unroll
                        for (int kw = 0; kw < 3; kw++)
                            acc[ot][ow] = fmaf(xr[ot + kh][ow + kw], wr[kh * 3 + kw], acc[ot][ow]);
        }
    }
#pragma unroll
    for (int ot = 0; ot < 2; ot++)
#pragma unroll
        for (int ow = 0; ow < 8; ow++)
            out[(((size_t)b * 128 + co0 + co_l) * 8 + oh0 + ot) * 8 + ow] = acc[ot][ow];
}

// ---------------- BN batch stats -> scale/shift ----------------
__global__ void k_bn_stats(const float* __restrict__ xin, const float* __restrict__ gamma,
                           const float* __restrict__ beta) {
    int c = blockIdx.x;
    int tid = threadIdx.x;
    float s = 0.f, s2 = 0.f;
    for (int i = tid; i < BB * 64; i += 256) {
        int b = i >> 6;
        int p = i & 63;
        float v = xin[(b * 128 + c) * 64 + p];
        s += v;
        s2 += v * v;
    }
    __shared__ float rs[256], rs2[256];
    rs[tid] = s; rs2[tid] = s2;
    __syncthreads();
    for (int o = 128; o > 0; o >>= 1) {
        if (tid < o) { rs[tid] += rs[tid + o]; rs2[tid] += rs2[tid + o]; }
        __syncthreads();
    }
    if (tid == 0) {
        float mean = rs[0] / 4096.f;
        float var  = rs2[0] / 4096.f - mean * mean;
        float sc   = gamma[c] * rsqrtf(var + 1e-5f);
        g_scale[c] = sc;
        g_shift[c] = beta[c] - mean * sc;
    }
}

__global__ void k_bn_relu(float* __restrict__ io) {
    int idx = blockIdx.x * 256 + threadIdx.x;
    int c = (idx >> 6) & 127;
    io[idx] = fmaxf(fmaf(g_scale[c], io[idx], g_shift[c]), 0.f);
}

__global__ void k_bn_add_relu(const float* __restrict__ o2, float* __restrict__ dskip) {
    int idx = blockIdx.x * 256 + threadIdx.x;
    int c = (idx >> 6) & 127;
    float h = fmaxf(fmaf(g_scale[c], o2[idx], g_shift[c]) + g_h[idx], 0.f);
    g_h[idx] = h;
    dskip[idx] += h;
}

// ---------------- fc: [64,8192] x [256,8192]^T + relu ----------------
__global__ void k_fc(const float* __restrict__ w, const float* __restrict__ bias,
                     float* __restrict__ outp) {
    int b = blockIdx.y;
    int j = blockIdx.x * 8 + (threadIdx.x >> 5);
    int lane = threadIdx.x & 31;
    const float4* a  = reinterpret_cast<const float4*>(g_h + (size_t)b * 8192);
    const float4* wr = reinterpret_cast<const float4*>(w + (size_t)j * 8192);
    float acc = 0.f;
    for (int i = lane; i < 2048; i += 32) {
        float4 av = a[i], wv = wr[i];
        acc += av.x * wv.x + av.y * wv.y + av.z * wv.z + av.w * wv.w;
    }
#pragma unroll
    for (int o = 16; o > 0; o >>= 1) acc += __shfl_down_sync(0xffffffffu, acc, o);
    if (lane == 0) outp[b * 256 + j] = fmaxf(acc + bias[j], 0.f);
}

// ---------------- launch ----------------
extern "C" void kernel_launch(void* const* d_in, const int* in_sizes, int n_in,
                              void* d_out, int out_size) {
    const float* x    = (const float*)d_in[0];
    const float* emb  = (const float*)d_in[1];
    const int*   xy   = (const int*)  d_in[2];
    const float* c1w  = (const float*)d_in[3];
    const float* pw   = (const float*)d_in[4];
    const float* pb   = (const float*)d_in[5];
    const float* ds1w = (const float*)d_in[6];
    const float* ds1b = (const float*)d_in[7];
    const float* ds2w = (const float*)d_in[8];
    const float* ds2b = (const float*)d_in[9];
    const float* ds3w = (const float*)d_in[10];
    const float* ds3b = (const float*)d_in[11];
    const float* rc1w = (const float*)d_in[12];
    const float* bn1g = (const float*)d_in[13];
    const float* bn1b = (const float*)d_in[14];
    const float* rc2w = (const float*)d_in[15];
    const float* bn2g = (const float*)d_in[16];
    const float* bn2b = (const float*)d_in[17];
    const float* fcw  = (const float*)d_in[18];
    const float* fcb  = (const float*)d_in[19];
    float* out = (float*)d_out;

    float *h1, *h2, *h3, *hh, *o1, *o2;
    cudaGetSymbolAddress((void**)&h1, g_h1);
    cudaGetSymbolAddress((void**)&h2, g_h2);
    cudaGetSymbolAddress((void**)&h3, g_h3);
    cudaGetSymbolAddress((void**)&hh, g_h);
    cudaGetSymbolAddress((void**)&o1, g_o1);
    cudaGetSymbolAddress((void**)&o2, g_o2);

    k_init_concat<<<(BB * 50 * 4096) / 256, 256>>>(x);
    k_scatter<<<(BB * NENT) / 8, 256>>>(emb, xy, c1w);
    k_proj<<<(BB * 4 * 4096) / 256, 256>>>(pw, pb);

    // ds1: 32->64, 64->32
    k_downconv<32, 64, 64, 2, 8, 2, 8><<<dim3(16, BB), 128>>>(h1, ds1w, ds1b, h2, nullptr);
    // ds2: 64->128, 32->16
    k_downconv<64, 32, 128, 2, 8, 2, 4><<<dim3(8, BB), 128>>>(h2, ds2w, ds2b, h3, nullptr);
    // ds3: 128->128, 16->8 ; mirror into d_out (map_skip init)
    k_downconv<128, 16, 128, 2, 4, 2, 4><<<dim3(4, BB), 128>>>(h3, ds3w, ds3b, hh, out);

    for (int i = 0; i < 4; i++) {
        const float* w1 = rc1w + (size_t)i * 128 * 128 * 9;
        const float* w2 = rc2w + (size_t)i * 128 * 128 * 9;
        k_resconv<<<dim3(4, BB), 128>>>(hh, w1, o1);
        k_bn_stats<<<128, 256>>>(o1, bn1g + i * 128, bn1b + i * 128);
        k_bn_relu<<<2048, 256>>>(o1);
        k_resconv<<<dim3(4, BB), 128>>>(o1, w2, o2);
        k_bn_stats<<<128, 256>>>(o2, bn2g + i * 128, bn2b + i * 128);
        k_bn_add_relu<<<2048, 256>>>(o2, out);
    }

    k_fc<<<dim3(32, BB), 256>>>(fcw, fcb, out + (size_t)BB * 128 * 64);
}

// round 2
// speedup vs baseline: 1.0029x; 1.0029x over previous
#include <cuda_runtime.h>
#include <cuda_bf16.h>

#define BB 64
#define NENT 512
#define DENT 256
#define WDIM 64

// ---------------- scratch (device globals; no allocations) ----------------
__device__ float g_h0[BB*50*WDIM*WDIM];   // concat [B,50,64,64]
__device__ float g_h1[BB*32*WDIM*WDIM];   // after project
__device__ float g_h2[BB*64*32*32];       // after ds1
__device__ float g_h3[BB*128*16*16];      // after ds2
__device__ float g_h [BB*128*8*8];        // running h (after ds3 / res blocks)
__device__ float g_o1[BB*128*8*8];        // res conv1 out
__device__ float g_o2[BB*128*8*8];        // res conv2 out
__device__ float g_scale[128];
__device__ float g_shift[128];

// ---------------- concat init: zero scatter channels, copy x ----------------
__global__ void k_init_concat(const float* __restrict__ x) {
    int idx = blockIdx.x * blockDim.x + threadIdx.x;
    const int per_b = 50 * 4096;
    int b = idx / per_b;
    int r = idx - b * per_b;
    int c = r >> 12;
    int p = r & 4095;
    g_h0[idx] = (c < 32) ? 0.f : x[(b * 18 + (c - 32)) * 4096 + p];
}

// ---------------- scatter: warp per entity ----------------
__global__ void k_scatter(const float* __restrict__ emb, const int* __restrict__ xy,
                          const float* __restrict__ w1) {
    __shared__ float s_wT[256 * 33];
    int tid = threadIdx.x;
    for (int i = tid; i < 32 * 256; i += blockDim.x) {
        int c = i >> 8;
        int d = i & 255;
        s_wT[d * 33 + c] = w1[i];
    }
    __syncthreads();
    int warp = blockIdx.x * (blockDim.x >> 5) + (tid >> 5);
    int lane = tid & 31;
    if (warp >= BB * NENT) return;
    int b = warp / NENT;
    int n = warp - b * NENT;
    const int* bits = xy + (size_t)(b * NENT + n) * 16;
    if (bits[0] == -1000000000) return;   // invalid entity contributes nothing
    int bit = (lane < 16) ? bits[lane] : 0;
    int contrib;
    if (lane < 8)       contrib = bit << (7 - lane);          // x bits
    else if (lane < 16) contrib = bit << (31 - lane);          // y bits at <<16
    else                contrib = 0;
    int pack = __reduce_add_sync(0xffffffffu, contrib);
    int xv = (pack & 0xffff) >> 2;
    int yv = (pack >> 16) >> 2;
    const float4* e4 = reinterpret_cast<const float4*>(emb + (size_t)(b * NENT + n) * 256);
    float acc = 0.f;
#pragma unroll 8
    for (int i = 0; i < 64; i++) {
        float4 v = e4[i];   // warp-uniform 16B load
        acc += v.x * s_wT[(4 * i + 0) * 33 + lane];
        acc += v.y * s_wT[(4 * i + 1) * 33 + lane];
        acc += v.z * s_wT[(4 * i + 2) * 33 + lane];
        acc += v.w * s_wT[(4 * i + 3) * 33 + lane];
    }
    acc = fmaxf(acc, 0.f);
    if (acc != 0.f)
        atomicAdd(&g_h0[(b * 50 + lane) * 4096 + yv * 64 + xv], acc);
}

// ---------------- project 1x1 conv 50->32 + relu ----------------
__global__ void k_proj(const float* __restrict__ pw, const float* __restrict__ pb) {
    __shared__ float s_pw[32 * 50];
    __shared__ float s_pb[32];
    int tid = threadIdx.x;
    for (int i = tid; i < 1600; i += blockDim.x) s_pw[i] = pw[i];
    if (tid < 32) s_pb[tid] = pb[tid];
    __syncthreads();
    int idx = blockIdx.x * blockDim.x + tid;   // (b, cg, p): p fastest
    int p  = idx & 4095;
    int cg = (idx >> 12) & 3;
    int b  = idx >> 14;
    float acc[8];
#pragma unroll
    for (int j = 0; j < 8; j++) acc[j] = 0.f;
    const float* src = g_h0 + (size_t)b * 50 * 4096 + p;
    for (int ci = 0; ci < 50; ci++) {
        float v = src[ci * 4096];
#pragma unroll
        for (int j = 0; j < 8; j++)
            acc[j] = fmaf(v, s_pw[(cg * 8 + j) * 50 + ci], acc[j]);
    }
    float* dst = g_h1 + ((size_t)b * 32 + cg * 8) * 4096 + p;
#pragma unroll
    for (int j = 0; j < 8; j++)
        dst[j * 4096] = fmaxf(acc[j] + s_pb[cg * 8 + j], 0.f);
}

// ---------------- down conv: k=4, s=2, p=1, +bias, +relu ----------------
template<int CIN, int HIN, int COUT, int TCO, int TOW, int TOH, int CC>
__global__ __launch_bounds__((COUT/TCO)*((HIN/2)/TOW))
void k_downconv(const float* __restrict__ in, const float* __restrict__ wt,
                const float* __restrict__ bias, float* __restrict__ out,
                float* __restrict__ out2) {
    constexpr int HO    = HIN / 2;
    constexpr int NCOG  = COUT / TCO;
    constexpr int NOWG  = HO / TOW;
    constexpr int NROWS = 2 * TOH + 2;
    constexpr int NTHR  = NCOG * NOWG;
    __shared__ float s_in[NROWS * CC * HIN];
    __shared__ float s_w[CC * 16 * (COUT + 1)];
    const int b   = blockIdx.y;
    const int oh0 = blockIdx.x * TOH;
    const int tid = threadIdx.x;
    const int cog = tid % NCOG;
    const int owg = tid / NCOG;
    const int co0 = cog * TCO;
    const int ow0 = owg * TOW;
    const int ihbase = 2 * oh0 - 1;
    float acc[TCO][TOH][TOW];
#pragma unroll
    for (int t = 0; t < TCO; t++)
#pragma unroll
        for (int o = 0; o < TOH; o++)
#pragma unroll
            for (int w = 0; w < TOW; w++) acc[t][o][w] = 0.f;

#pragma unroll 1
    for (int ci0 = 0; ci0 < CIN; ci0 += CC) {
        __syncthreads();
        for (int i = tid; i < NROWS * CC * HIN; i += NTHR) {
            int r   = i / (CC * HIN);
            int rem = i - r * CC * HIN;
            int cc  = rem / HIN;
            int xx  = rem - cc * HIN;
            int ih  = ihbase + r;
            s_in[i] = (ih >= 0 && ih < HIN)
                    ? in[(((size_t)b * CIN + ci0 + cc) * HIN + ih) * HIN + xx] : 0.f;
        }
        for (int i = tid; i < CC * 16 * COUT; i += NTHR) {
            int co  = i / (CC * 16);
            int k16 = i - co * CC * 16;
            s_w[k16 * (COUT + 1) + co] = wt[((size_t)co * CIN + ci0) * 16 + k16];
        }
        __syncthreads();
#pragma unroll 1
        for (int cc = 0; cc < CC; cc++) {
#pragma unroll
            for (int kh = 0; kh < 4; kh++) {
                float wr[TCO][4];
#pragma unroll
                for (int t = 0; t < TCO; t++)
#pragma unroll
                    for (int kw = 0; kw < 4; kw++)
                        wr[t][kw] = s_w[(cc * 16 + kh * 4 + kw) * (COUT + 1) + co0 + t];
#pragma unroll
                for (int ot = 0; ot < TOH; ot++) {
                    const float* srow = &s_in[((2 * ot + kh) * CC + cc) * HIN];
                    float xr[2 * TOW + 2];
#pragma unroll
                    for (int j = 0; j < 2 * TOW + 2; j++) {
                        int iw = 2 * ow0 - 1 + j;
                        xr[j] = (iw >= 0 && iw < HIN) ? srow[iw] : 0.f;
                    }
#pragma unroll
                    for (int t = 0; t < TCO; t++)
#pragma unroll
                        for (int w = 0; w < TOW; w++)
#pragma unroll
                            for (int kw = 0; kw < 4; kw++)
                                acc[t][ot][w] = fmaf(xr[2 * w + kw], wr[t][kw], acc[t][ot][w]);
                }
            }
        }
    }
#pragma unroll
    for (int t = 0; t < TCO; t++) {
        float bv = bias[co0 + t];
#pragma unroll
        for (int ot = 0; ot < TOH; ot++)
#pragma unroll
            for (int w = 0; w < TOW; w++) {
                float v = fmaxf(acc[t][ot][w] + bv, 0.f);
                size_t o = (((size_t)b * COUT + co0 + t) * HO + oh0 + ot) * HO + ow0 + w;
                out[o] = v;
                if (out2) out2[o] = v;
            }
    }
}

// ---------------- res conv 3x3 p1 on 8x8, 128->128, raw (BN after) ----------------
__global__ __launch_bounds__(128)
void k_resconv(const float* __restrict__ in, const float* __restrict__ wt,
               float* __restrict__ out) {
    constexpr int COC = 32;
    constexpr int CC  = 16;
    __shared__ float s_img[CC * 100];           // [cc][10 rows][10 cols], zero-padded
    __shared__ float s_w[CC * 9 * (COC + 1)];
    const int b    = blockIdx.y;
    const int co0  = blockIdx.x * COC;
    const int tid  = threadIdx.x;
    const int co_l = tid & 31;
    const int ohp  = tid >> 5;
    const int oh0  = ohp * 2;
    float acc[2][8];
#pragma unroll
    for (int o = 0; o < 2; o++)
#pragma unroll
        for (int w = 0; w < 8; w++) acc[o][w] = 0.f;

#pragma unroll 1
    for (int ci0 = 0; ci0 < 128; ci0 += CC) {
        __syncthreads();
        for (int i = tid; i < CC * 100; i += 128) {
            int cc  = i / 100;
            int rem = i - cc * 100;
            int r   = rem / 10;
            int cl  = rem - r * 10;
            int ih = r - 1, iw = cl - 1;
            s_img[i] = (ih >= 0 && ih < 8 && iw >= 0 && iw < 8)
                     ? in[(((size_t)b * 128 + ci0 + cc) * 8 + ih) * 8 + iw] : 0.f;
        }
        for (int i = tid; i < CC * 9 * COC; i += 128) {
            int co = i / (CC * 9);
            int k9 = i - co * CC * 9;
            s_w[k9 * (COC + 1) + co] = wt[((size_t)(co0 + co) * 128 + ci0) * 9 + k9];
        }
        __syncthreads();
#pragma unroll 1
        for (int cc = 0; cc < CC; cc++) {
            float wr[9];
#pragma unroll
            for (int k = 0; k < 9; k++) wr[k] = s_w[(cc * 9 + k) * (COC + 1) + co_l];
            float xr[4][10];
#pragma unroll
            for (int r = 0; r < 4; r++)
#pragma unroll
                for (int cl = 0; cl < 10; cl++)
                    xr[r][cl] = s_img[cc * 100 + (oh0 + r) * 10 + cl];
#pragma unroll
            for (int ot = 0; ot < 2; ot++)
#pragma unroll
                for (int kh = 0; kh < 3; kh++)
#pragma unroll
                    for (int ow = 0; ow < 8; ow++)
#pragma unroll
                        for (int kw = 0; kw < 3; kw++)
                            acc[ot][ow] = fmaf(xr[ot + kh][ow + kw], wr[kh * 3 + kw], acc[ot][ow]);
        }
    }
#pragma unroll
    for (int ot = 0; ot < 2; ot++)
#pragma unroll
        for (int ow = 0; ow < 8; ow++)
            out[(((size_t)b * 128 + co0 + co_l) * 8 + oh0 + ot) * 8 + ow] = acc[ot][ow];
}

// ---------------- BN batch stats -> scale/shift ----------------
__global__ void k_bn_stats(const float* __restrict__ xin, const float* __restrict__ gamma,
                           const float* __restrict__ beta) {
    int c = blockIdx.x;
    int tid = threadIdx.x;
    float s = 0.f, s2 = 0.f;
    for (int i = tid; i < BB * 64; i += 256) {
        int b = i >> 6;
        int p = i & 63;
        float v = xin[(b * 128 + c) * 64 + p];
        s += v;
        s2 += v * v;
    }
    __shared__ float rs[256], rs2[256];
    rs[tid] = s; rs2[tid] = s2;
    __syncthreads();
    for (int o = 128; o > 0; o >>= 1) {
        if (tid < o) { rs[tid] += rs[tid + o]; rs2[tid] += rs2[tid + o]; }
        __syncthreads();
    }
    if (tid == 0) {
        float mean = rs[0] / 4096.f;
        float var  = rs2[0] / 4096.f - mean * mean;
        float sc   = gamma[c] * rsqrtf(var + 1e-5f);
        g_scale[c] = sc;
        g_shift[c] = beta[c] - mean * sc;
    }
}

__global__ void k_bn_relu(float* __restrict__ io) {
    int idx = blockIdx.x * 256 + threadIdx.x;
    int c = (idx >> 6) & 127;
    io[idx] = fmaxf(fmaf(g_scale[c], io[idx], g_shift[c]), 0.f);
}

__global__ void k_bn_add_relu(const float* __restrict__ o2, float* __restrict__ dskip) {
    int idx = blockIdx.x * 256 + threadIdx.x;
    int c = (idx >> 6) & 127;
    float h = fmaxf(fmaf(g_scale[c], o2[idx], g_shift[c]) + g_h[idx], 0.f);
    g_h[idx] = h;
    dskip[idx] += h;
}

// ---------------- fc: [64,8192] x [256,8192]^T + relu ----------------
__global__ void k_fc(const float* __restrict__ w, const float* __restrict__ bias,
                     float* __restrict__ outp) {
    int b = blockIdx.y;
    int j = blockIdx.x * 8 + (threadIdx.x >> 5);
    int lane = threadIdx.x & 31;
    const float4* a  = reinterpret_cast<const float4*>(g_h + (size_t)b * 8192);
    const float4* wr = reinterpret_cast<const float4*>(w + (size_t)j * 8192);
    float acc = 0.f;
    for (int i = lane; i < 2048; i += 32) {
        float4 av = a[i], wv = wr[i];
        acc += av.x * wv.x + av.y * wv.y + av.z * wv.z + av.w * wv.w;
    }
#pragma unroll
    for (int o = 16; o > 0; o >>= 1) acc += __shfl_down_sync(0xffffffffu, acc, o);
    if (lane == 0) outp[b * 256 + j] = fmaxf(acc + bias[j], 0.f);
}

// ---------------- launch ----------------
extern "C" void kernel_launch(void* const* d_in, const int* in_sizes, int n_in,
                              void* d_out, int out_size) {
    const float* x    = (const float*)d_in[0];
    const float* emb  = (const float*)d_in[1];
    const int*   xy   = (const int*)  d_in[2];
    const float* c1w  = (const float*)d_in[3];
    const float* pw   = (const float*)d_in[4];
    const float* pb   = (const float*)d_in[5];
    const float* ds1w = (const float*)d_in[6];
    const float* ds1b = (const float*)d_in[7];
    const float* ds2w = (const float*)d_in[8];
    const float* ds2b = (const float*)d_in[9];
    const float* ds3w = (const float*)d_in[10];
    const float* ds3b = (const float*)d_in[11];
    const float* rc1w = (const float*)d_in[12];
    const float* bn1g = (const float*)d_in[13];
    const float* bn1b = (const float*)d_in[14];
    const float* rc2w = (const float*)d_in[15];
    const float* bn2g = (const float*)d_in[16];
    const float* bn2b = (const float*)d_in[17];
    const float* fcw  = (const float*)d_in[18];
    const float* fcb  = (const float*)d_in[19];
    float* out = (float*)d_out;

    float *h1, *h2, *h3, *hh, *o1, *o2;
    cudaGetSymbolAddress((void**)&h1, g_h1);
    cudaGetSymbolAddress((void**)&h2, g_h2);
    cudaGetSymbolAddress((void**)&h3, g_h3);
    cudaGetSymbolAddress((void**)&hh, g_h);
    cudaGetSymbolAddress((void**)&o1, g_o1);
    cudaGetSymbolAddress((void**)&o2, g_o2);

    k_init_concat<<<(BB * 50 * 4096) / 256, 256>>>(x);
    k_scatter<<<(BB * NENT) / 8, 256>>>(emb, xy, c1w);
    k_proj<<<(BB * 4 * 4096) / 256, 256>>>(pw, pb);

    // ds1: 32->64, 64->32
    k_downconv<32, 64, 64, 2, 8, 2, 8><<<dim3(16, BB), 128>>>(h1, ds1w, ds1b, h2, nullptr);
    // ds2: 64->128, 32->16
    k_downconv<64, 32, 128, 2, 8, 2, 4><<<dim3(8, BB), 128>>>(h2, ds2w, ds2b, h3, nullptr);
    // ds3: 128->128, 16->8 ; mirror into d_out (map_skip init)
    k_downconv<128, 16, 128, 2, 4, 2, 4><<<dim3(4, BB), 128>>>(h3, ds3w, ds3b, hh, out);

    for (int i = 0; i < 4; i++) {
        const float* w1 = rc1w + (size_t)i * 128 * 128 * 9;
        const float* w2 = rc2w + (size_t)i * 128 * 128 * 9;
        k_resconv<<<dim3(4, BB), 128>>>(hh, w1, o1);
        k_bn_stats<<<128, 256>>>(o1, bn1g + i * 128, bn1b + i * 128);
        k_bn_relu<<<2048, 256>>>(o1);
        k_resconv<<<dim3(4, BB), 128>>>(o1, w2, o2);
        k_bn_stats<<<128, 256>>>(o2, bn2g + i * 128, bn2b + i * 128);
        k_bn_add_relu<<<2048, 256>>>(o2, out);
    }

    k_fc<<<dim3(32, BB), 256>>>(fcw, fcb, out + (size_t)BB * 128 * 64);
}

// round 3
// speedup vs baseline: 1.5575x; 1.5529x over previous
#include <cuda_runtime.h>
#include <cuda_bf16.h>

typedef unsigned long long ull;
#define BB 64
#define NENT 512

// ---------------- device scratch ----------------
__device__ float g_scat[BB*32*4096];
__device__ float g_h1[BB*32*4096];
__device__ float g_h2[BB*64*1024];
__device__ float g_h3[BB*128*256];
__device__ float g_h [BB*128*64];
__device__ float g_o1[BB*128*64];
__device__ float g_o2[BB*128*64];
__device__ float g_part[4*BB*128*64];
__device__ float g_scale[128], g_shift[128];
__device__ float g_wt1[32*16*64];
__device__ float g_wt2[64*16*128];
__device__ float g_wt3[128*16*128];
__device__ float g_rwt[8*128*9*128];

// ---------------- f32x2 helpers (bit-exact fp32 pairs) ----------------
__device__ __forceinline__ ull pk2(float v) {
    ull r; asm("mov.b64 %0, {%1,%2};" : "=l"(r) : "f"(v), "f"(v)); return r;
}
__device__ __forceinline__ void fma2(ull& d, ull a, ull b) {
    asm("fma.rn.f32x2 %0, %1, %2, %0;" : "+l"(d) : "l"(a), "l"(b));
}
__device__ __forceinline__ void upk(ull v, float& lo, float& hi) {
    asm("mov.b64 {%0,%1}, %2;" : "=f"(lo), "=f"(hi) : "l"(v));
}

// ---------------- small utility kernels ----------------
__global__ void k_zero4(float4* p) {
    p[blockIdx.x * 256 + threadIdx.x] = make_float4(0.f, 0.f, 0.f, 0.f);
}

// [co][ci][k16] -> [ci][k16][co]
template<int CIN, int COUT>
__global__ void k_tr_ds(const float* __restrict__ w, float* __restrict__ o) {
    int idx = blockIdx.x * 256 + threadIdx.x;
    if (idx >= CIN * 16 * COUT) return;
    int co = idx % COUT; int t = idx / COUT; int k = t % 16; int ci = t / 16;
    o[idx] = w[(co * CIN + ci) * 16 + k];
}

// res weights: [i][co][ci][k9] -> g_rwt[i'][(ci*9+k)*128+co], i'=i for conv1, 4+i for conv2
__global__ void k_tr_res(const float* __restrict__ w1, const float* __restrict__ w2) {
    int idx = blockIdx.x * 256 + threadIdx.x;
    const int half = 589824;
    if (idx >= 2 * half) return;
    const float* s = (idx < half) ? w1 : w2;
    int id = (idx < half) ? idx : idx - half;
    int co = id & 127; int t = id >> 7; int k = t % 9; int t2 = t / 9;
    int ci = t2 & 127; int i = t2 >> 7;
    int dsti = (idx < half) ? i : (4 + i);
    g_rwt[(size_t)dsti * 147456 + (ci * 9 + k) * 128 + co] =
        s[(((size_t)i * 128 + co) * 128 + ci) * 9 + k];
}

// ---------------- scatter: warp per entity ----------------
__global__ void k_scatter(const float* __restrict__ emb, const int* __restrict__ xy,
                          const float* __restrict__ w1) {
    __shared__ float s_wT[256 * 33];
    int tid = threadIdx.x;
    for (int i = tid; i < 32 * 256; i += blockDim.x) {
        int c = i >> 8, d = i & 255;
        s_wT[d * 33 + c] = w1[i];
    }
    __syncthreads();
    int warp = blockIdx.x * (blockDim.x >> 5) + (tid >> 5);
    int lane = tid & 31;
    if (warp >= BB * NENT) return;
    int b = warp / NENT, n = warp - b * NENT;
    const int* bits = xy + (size_t)(b * NENT + n) * 16;
    if (bits[0] == -1000000000) return;
    int bit = (lane < 16) ? bits[lane] : 0;
    int contrib;
    if (lane < 8)       contrib = bit << (7 - lane);
    else if (lane < 16) contrib = bit << (31 - lane);
    else                contrib = 0;
    int pack = __reduce_add_sync(0xffffffffu, contrib);
    int xv = (pack & 0xffff) >> 2;
    int yv = (pack >> 16) >> 2;
    const float4* e4 = reinterpret_cast<const float4*>(emb + (size_t)(b * NENT + n) * 256);
    float acc = 0.f;
#pragma unroll 8
    for (int i = 0; i < 64; i++) {
        float4 v = e4[i];
        acc += v.x * s_wT[(4 * i + 0) * 33 + lane];
        acc += v.y * s_wT[(4 * i + 1) * 33 + lane];
        acc += v.z * s_wT[(4 * i + 2) * 33 + lane];
        acc += v.w * s_wT[(4 * i + 3) * 33 + lane];
    }
    acc = fmaxf(acc, 0.f);
    if (acc != 0.f)
        atomicAdd(&g_scat[((size_t)b * 32 + lane) * 4096 + yv * 64 + xv], acc);
}

// ---------------- project 1x1 conv (scat 32ch + x 18ch) -> 32, +relu ----------------
__global__ void k_proj(const float* __restrict__ x, const float* __restrict__ pw,
                       const float* __restrict__ pb) {
    __shared__ float s_pw[32 * 50];
    __shared__ float s_pb[32];
    int tid = threadIdx.x;
    for (int i = tid; i < 1600; i += blockDim.x) s_pw[i] = pw[i];
    if (tid < 32) s_pb[tid] = pb[tid];
    __syncthreads();
    int idx = blockIdx.x * blockDim.x + tid;
    int p  = idx & 4095;
    int cg = (idx >> 12) & 3;
    int b  = idx >> 14;
    float acc[8];
#pragma unroll
    for (int j = 0; j < 8; j++) acc[j] = 0.f;
    const float* srcs = g_scat + (size_t)b * 32 * 4096 + p;
#pragma unroll 1
    for (int ci = 0; ci < 32; ci++) {
        float v = srcs[ci * 4096];
#pragma unroll
        for (int j = 0; j < 8; j++)
            acc[j] = fmaf(v, s_pw[(cg * 8 + j) * 50 + ci], acc[j]);
    }
    const float* srcx = x + (size_t)b * 18 * 4096 + p;
#pragma unroll 1
    for (int cx = 0; cx < 18; cx++) {
        float v = srcx[cx * 4096];
#pragma unroll
        for (int j = 0; j < 8; j++)
            acc[j] = fmaf(v, s_pw[(cg * 8 + j) * 50 + 32 + cx], acc[j]);
    }
    float* dst = g_h1 + ((size_t)b * 32 + cg * 8) * 4096 + p;
#pragma unroll
    for (int j = 0; j < 8; j++)
        dst[j * 4096] = fmaxf(acc[j] + s_pb[cg * 8 + j], 0.f);
}

// ---------------- down conv k=4 s=2 p=1, +bias +relu, f32x2 co-pairs ----------------
template<int CIN, int HIN, int COUT, int TOW, int TOH, int CC, int NTHR>
__global__ __launch_bounds__(NTHR)
void k_down(const float* __restrict__ in, const float* __restrict__ wT,
            const float* __restrict__ bias, float* __restrict__ out,
            float* __restrict__ out2) {
    constexpr int HO    = HIN / 2;
    constexpr int NCOG  = COUT / 2;
    constexpr int NROWS = 2 * TOH + 2;
    static_assert(NTHR == NCOG * (HO / TOW), "thread count");
    __shared__ float s_in[NROWS * CC * HIN];
    __shared__ float s_w[CC * 16 * COUT];
    const int tid = threadIdx.x;
    const int b = blockIdx.y, oh0 = blockIdx.x * TOH;
    const int cog = tid % NCOG, owg = tid / NCOG;
    const int co0 = 2 * cog, ow0 = owg * TOW;
    const int ihb = 2 * oh0 - 1;
    ull acc[TOH][TOW];
#pragma unroll
    for (int o = 0; o < TOH; o++)
#pragma unroll
        for (int w = 0; w < TOW; w++) acc[o][w] = 0ull;

#pragma unroll 1
    for (int ci0 = 0; ci0 < CIN; ci0 += CC) {
        __syncthreads();
        for (int i = tid; i < NROWS * CC * HIN; i += NTHR) {
            int r   = i / (CC * HIN);
            int rem = i - r * CC * HIN;
            int cc  = rem / HIN;
            int xx  = rem - cc * HIN;
            int ih  = ihb + r;
            s_in[i] = (ih >= 0 && ih < HIN)
                    ? in[(((size_t)b * CIN + ci0 + cc) * HIN + ih) * HIN + xx] : 0.f;
        }
        const float4* wsrc = reinterpret_cast<const float4*>(wT + (size_t)ci0 * 16 * COUT);
        float4* wdst = reinterpret_cast<float4*>(s_w);
        for (int i = tid; i < CC * 16 * COUT / 4; i += NTHR) wdst[i] = wsrc[i];
        __syncthreads();
#pragma unroll 1
        for (int cc = 0; cc < CC; cc++) {
#pragma unroll
            for (int r = 0; r < NROWS; r++) {
                const float* row = &s_in[(r * CC + cc) * HIN];
                ull xd[2 * TOW + 2];
#pragma unroll
                for (int j = 0; j < 2 * TOW + 2; j++) {
                    int iw = 2 * ow0 - 1 + j;
                    float v = (iw >= 0 && iw < HIN) ? row[iw] : 0.f;
                    xd[j] = pk2(v);
                }
#pragma unroll
                for (int ot = 0; ot < TOH; ot++) {
                    constexpr int four = 4;
                    int kh = r - 2 * ot;
                    if (kh >= 0 && kh < four) {
                        ull wpk[4];
#pragma unroll
                        for (int kw = 0; kw < 4; kw++)
                            wpk[kw] = *reinterpret_cast<const ull*>(
                                &s_w[(cc * 16 + kh * 4 + kw) * COUT + co0]);
#pragma unroll
                        for (int w = 0; w < TOW; w++)
#pragma unroll
                            for (int kw = 0; kw < 4; kw++)
                                fma2(acc[ot][w], xd[2 * w + kw], wpk[kw]);
                    }
                }
            }
        }
    }
    float bv0 = bias[co0], bv1 = bias[co0 + 1];
#pragma unroll
    for (int ot = 0; ot < TOH; ot++)
#pragma unroll
        for (int w = 0; w < TOW; w++) {
            float lo, hi; upk(acc[ot][w], lo, hi);
            float v0 = fmaxf(lo + bv0, 0.f);
            float v1 = fmaxf(hi + bv1, 0.f);
            size_t o0 = (((size_t)b * COUT + co0) * HO + oh0 + ot) * HO + ow0 + w;
            out[o0] = v0;
            out[o0 + (size_t)HO * HO] = v1;
            if (out2) { out2[o0] = v0; out2[o0 + (size_t)HO * HO] = v1; }
        }
}

// ---------------- res conv 3x3 p1 on 8x8, ci-split x4, f32x2 ----------------
__global__ __launch_bounds__(128)
void k_res(const float* __restrict__ in, const float* __restrict__ wT,
           float* __restrict__ part) {
    __shared__ float s_img[16 * 100];
    __shared__ float s_w[16 * 9 * 32];
    const int tid = threadIdx.x;
    const int b = blockIdx.y;
    const int co_base = blockIdx.x * 32;
    const int zi = blockIdx.z;
    const int copl = tid & 15, ohp = tid >> 4;
    const int co0 = co_base + 2 * copl;
    ull acc[8];
#pragma unroll
    for (int w = 0; w < 8; w++) acc[w] = 0ull;

#pragma unroll 1
    for (int c2 = 0; c2 < 2; c2++) {
        int cib = zi * 32 + c2 * 16;
        __syncthreads();
        // zero padded borders (36 cells per ci)
        for (int i = tid; i < 16 * 36; i += 128) {
            int ci = i / 36, e = i - 36 * ci;
            int ofs;
            if (e < 10)      ofs = e;
            else if (e < 20) ofs = 90 + (e - 10);
            else { int r = ((e - 20) >> 1) + 1; int c = ((e - 20) & 1) * 9; ofs = r * 10 + c; }
            s_img[ci * 100 + ofs] = 0.f;
        }
        // interior rows
        for (int i = tid; i < 128; i += 128) {
            int ci = i >> 3, r = i & 7;
            const float4* src = reinterpret_cast<const float4*>(
                in + (((size_t)(b * 128 + cib + ci)) * 8 + r) * 8);
            float4 v0 = src[0], v1 = src[1];
            float* d = &s_img[ci * 100 + (r + 1) * 10 + 1];
            d[0] = v0.x; d[1] = v0.y; d[2] = v0.z; d[3] = v0.w;
            d[4] = v1.x; d[5] = v1.y; d[6] = v1.z; d[7] = v1.w;
        }
        // weights: 16 ci x 9 k x 32 co (co slice contiguous 128B per (ci,k))
        for (int i = tid; i < 16 * 9 * 8; i += 128) {
            int c8 = i & 7; int t = i >> 3; int k = t % 9; int ciL = t / 9;
            *reinterpret_cast<float4*>(&s_w[(ciL * 9 + k) * 32 + 4 * c8]) =
                *reinterpret_cast<const float4*>(
                    wT + ((size_t)(cib + ciL) * 9 + k) * 128 + co_base + 4 * c8);
        }
        __syncthreads();
#pragma unroll 1
        for (int ciL = 0; ciL < 16; ciL++) {
            ull wp[9];
#pragma unroll
            for (int k = 0; k < 9; k++)
                wp[k] = *reinterpret_cast<const ull*>(&s_w[(ciL * 9 + k) * 32 + 2 * copl]);
#pragma unroll
            for (int kh = 0; kh < 3; kh++) {
                const float* row = &s_img[ciL * 100 + (ohp + kh) * 10];
                ull xd[10];
#pragma unroll
                for (int j = 0; j < 10; j++) xd[j] = pk2(row[j]);
#pragma unroll
                for (int ow = 0; ow < 8; ow++)
#pragma unroll
                    for (int kw = 0; kw < 3; kw++)
                        fma2(acc[ow], xd[ow + kw], wp[kh * 3 + kw]);
            }
        }
    }
    float* dst = part + (size_t)zi * 524288 + ((size_t)(b * 128 + co0)) * 64 + ohp * 8;
#pragma unroll
    for (int ow = 0; ow < 8; ow++) {
        float lo, hi; upk(acc[ow], lo, hi);
        dst[ow] = lo; dst[64 + ow] = hi;
    }
}

// ---------------- BN: sum 4 partials + batch stats -> scale/shift ----------------
__global__ void k_bn_stats(const float* __restrict__ gamma, const float* __restrict__ beta,
                           float* __restrict__ osum) {
    int c = blockIdx.x, tid = threadIdx.x;
    float s = 0.f, s2 = 0.f;
    for (int i = tid; i < BB * 64; i += 256) {
        int b = i >> 6, p = i & 63;
        size_t idx = ((size_t)(b * 128 + c)) * 64 + p;
        float v = g_part[idx] + g_part[524288 + idx] + g_part[1048576 + idx]
                + g_part[1572864 + idx];
        osum[idx] = v;
        s += v; s2 += v * v;
    }
    __shared__ float rs[256], rs2[256];
    rs[tid] = s; rs2[tid] = s2;
    __syncthreads();
    for (int o = 128; o > 0; o >>= 1) {
        if (tid < o) { rs[tid] += rs[tid + o]; rs2[tid] += rs2[tid + o]; }
        __syncthreads();
    }
    if (tid == 0) {
        float mean = rs[0] / 4096.f;
        float var  = rs2[0] / 4096.f - mean * mean;
        float sc   = gamma[c] * rsqrtf(var + 1e-5f);
        g_scale[c] = sc;
        g_shift[c] = beta[c] - mean * sc;
    }
}

__global__ void k_bn_relu(float* __restrict__ io) {
    int idx = blockIdx.x * 256 + threadIdx.x;
    int c = (idx >> 6) & 127;
    io[idx] = fmaxf(fmaf(g_scale[c], io[idx], g_shift[c]), 0.f);
}

__global__ void k_bn_add_relu(const float* __restrict__ o2, float* __restrict__ dskip) {
    int idx = blockIdx.x * 256 + threadIdx.x;
    int c = (idx >> 6) & 127;
    float h = fmaxf(fmaf(g_scale[c], o2[idx], g_shift[c]) + g_h[idx], 0.f);
    g_h[idx] = h;
    dskip[idx] += h;
}

// ---------------- fc: A row in smem, 32 j per block ----------------
__global__ __launch_bounds__(256)
void k_fc(const float* __restrict__ w, const float* __restrict__ bias,
          float* __restrict__ outp) {
    __shared__ float s_a[8192];
    int jg = blockIdx.x, b = blockIdx.y;
    int tid = threadIdx.x;
    const float4* src = reinterpret_cast<const float4*>(g_h + (size_t)b * 8192);
    float4* sd = reinterpret_cast<float4*>(s_a);
    for (int i = tid; i < 2048; i += 256) sd[i] = src[i];
    __syncthreads();
    int wrp = tid >> 5, lane = tid & 31;
#pragma unroll 1
    for (int q = 0; q < 4; q++) {
        int j = jg * 32 + wrp * 4 + q;
        const float4* wr = reinterpret_cast<const float4*>(w + (size_t)j * 8192);
        const float4* a4 = reinterpret_cast<const float4*>(s_a);
        float acc = 0.f;
#pragma unroll 4
        for (int i = lane; i < 2048; i += 32) {
            float4 wv = wr[i], av = a4[i];
            acc += wv.x * av.x + wv.y * av.y + wv.z * av.z + wv.w * av.w;
        }
#pragma unroll
        for (int o = 16; o > 0; o >>= 1) acc += __shfl_down_sync(0xffffffffu, acc, o);
        if (lane == 0) outp[(size_t)b * 256 + j] = fmaxf(acc + bias[j], 0.f);
    }
}

// ---------------- launch ----------------
extern "C" void kernel_launch(void* const* d_in, const int* in_sizes, int n_in,
                              void* d_out, int out_size) {
    const float* x    = (const float*)d_in[0];
    const float* emb  = (const float*)d_in[1];
    const int*   xy   = (const int*)  d_in[2];
    const float* c1w  = (const float*)d_in[3];
    const float* pw   = (const float*)d_in[4];
    const float* pb   = (const float*)d_in[5];
    const float* ds1w = (const float*)d_in[6];
    const float* ds1b = (const float*)d_in[7];
    const float* ds2w = (const float*)d_in[8];
    const float* ds2b = (const float*)d_in[9];
    const float* ds3w = (const float*)d_in[10];
    const float* ds3b = (const float*)d_in[11];
    const float* rc1w = (const float*)d_in[12];
    const float* bn1g = (const float*)d_in[13];
    const float* bn1b = (const float*)d_in[14];
    const float* rc2w = (const float*)d_in[15];
    const float* bn2g = (const float*)d_in[16];
    const float* bn2b = (const float*)d_in[17];
    const float* fcw  = (const float*)d_in[18];
    const float* fcb  = (const float*)d_in[19];
    float* out = (float*)d_out;

    float *scat, *h1, *h2, *h3, *hh, *o1, *o2, *partp, *wt1, *wt2, *wt3, *rwt;
    cudaGetSymbolAddress((void**)&scat,  g_scat);
    cudaGetSymbolAddress((void**)&h1,    g_h1);
    cudaGetSymbolAddress((void**)&h2,    g_h2);
    cudaGetSymbolAddress((void**)&h3,    g_h3);
    cudaGetSymbolAddress((void**)&hh,    g_h);
    cudaGetSymbolAddress((void**)&o1,    g_o1);
    cudaGetSymbolAddress((void**)&o2,    g_o2);
    cudaGetSymbolAddress((void**)&partp, g_part);
    cudaGetSymbolAddress((void**)&wt1,   g_wt1);
    cudaGetSymbolAddress((void**)&wt2,   g_wt2);
    cudaGetSymbolAddress((void**)&wt3,   g_wt3);
    cudaGetSymbolAddress((void**)&rwt,   g_rwt);

    // weight transposes (cheap, every launch; deterministic)
    k_tr_ds<32, 64>  <<<(32 * 16 * 64 + 255) / 256, 256>>>(ds1w, wt1);
    k_tr_ds<64, 128> <<<(64 * 16 * 128 + 255) / 256, 256>>>(ds2w, wt2);
    k_tr_ds<128, 128><<<(128 * 16 * 128 + 255) / 256, 256>>>(ds3w, wt3);
    k_tr_res<<<(2 * 589824 + 255) / 256, 256>>>(rc1w, rc2w);

    k_zero4<<<8192, 256>>>(reinterpret_cast<float4*>(scat));
    k_scatter<<<(BB * NENT) / 8, 256>>>(emb, xy, c1w);
    k_proj<<<(BB * 4 * 4096) / 256, 256>>>(x, pw, pb);

    // ds1: 32->64 @64->32
    k_down<32, 64, 64, 4, 2, 8, 256><<<dim3(16, BB), 256>>>(h1, wt1, ds1b, h2, nullptr);
    // ds2: 64->128 @32->16
    k_down<64, 32, 128, 4, 2, 4, 256><<<dim3(8, BB), 256>>>(h2, wt2, ds2b, h3, nullptr);
    // ds3: 128->128 @16->8 ; mirror into d_out (map_skip init)
    k_down<128, 16, 128, 4, 2, 4, 128><<<dim3(4, BB), 128>>>(h3, wt3, ds3b, hh, out);

    for (int i = 0; i < 4; i++) {
        k_res<<<dim3(4, BB, 4), 128>>>(hh, rwt + (size_t)i * 147456, partp);
        k_bn_stats<<<128, 256>>>(bn1g + i * 128, bn1b + i * 128, o1);
        k_bn_relu<<<2048, 256>>>(o1);
        k_res<<<dim3(4, BB, 4), 128>>>(o1, rwt + (size_t)(4 + i) * 147456, partp);
        k_bn_stats<<<128, 256>>>(bn2g + i * 128, bn2b + i * 128, o2);
        k_bn_add_relu<<<2048, 256>>>(o2, out);
    }

    k_fc<<<dim3(8, BB), 256>>>(fcw, fcb, out + (size_t)BB * 128 * 64);
}